// round 2
// baseline (speedup 1.0000x reference)
#include <cuda_runtime.h>
#include <math.h>

// Problem constants
constexpr int I_SZ = 256;   // groups
constexpr int D_SZ = 128;   // per-group dim
constexpr int B_SZ = 1024;  // batch
constexpr int HD   = I_SZ * D_SZ;  // 32768
constexpr int TB   = 64;    // batch rows per block tile
constexpr int NTHREADS = 256;

// dynamic smem layout (floats):
//   a_s  [TB][D]   : A tile (hg or rh)                  8192
//   U_s  [D][D]    : current U operand                 16384
//   w1_s [D], w2_s[D], b1_s[D], b2_s[D]                  512
//   x_s  [TB]                                             64
constexpr int SMEM_FLOATS = TB * D_SZ + D_SZ * D_SZ + 4 * D_SZ + TB;
constexpr size_t SMEM_BYTES = (size_t)SMEM_FLOATS * sizeof(float);

__device__ __forceinline__ float sigmoid_fast(float x) {
    return 1.0f / (1.0f + __expf(-x));
}

// Shared GEMM core: acc[4][8] += A_tile(rows r0..r0+3) * U_s (K=128)
#define GEMM_CORE(a_s, U_s, acc, r0, c0)                                        \
    do {                                                                        \
        _Pragma("unroll 4")                                                     \
        for (int k = 0; k < D_SZ; k++) {                                        \
            float a0 = (a_s)[((r0) + 0) * D_SZ + k];                            \
            float a1 = (a_s)[((r0) + 1) * D_SZ + k];                            \
            float a2 = (a_s)[((r0) + 2) * D_SZ + k];                            \
            float a3 = (a_s)[((r0) + 3) * D_SZ + k];                            \
            float4 bA = *(const float4*)&(U_s)[k * D_SZ + (c0)];                \
            float4 bB = *(const float4*)&(U_s)[k * D_SZ + (c0) + 4];            \
            float bv[8] = {bA.x, bA.y, bA.z, bA.w, bB.x, bB.y, bB.z, bB.w};     \
            _Pragma("unroll")                                                   \
            for (int cc = 0; cc < 8; cc++) {                                    \
                acc[0][cc] = fmaf(a0, bv[cc], acc[0][cc]);                      \
                acc[1][cc] = fmaf(a1, bv[cc], acc[1][cc]);                      \
                acc[2][cc] = fmaf(a2, bv[cc], acc[2][cc]);                      \
                acc[3][cc] = fmaf(a3, bv[cc], acc[3][cc]);                      \
            }                                                                   \
        }                                                                       \
    } while (0)

// Phase 1: r = sigmoid(x*W_r + hg@U_r + b_r); z = sigmoid(x*W_z + hg@U_z + b_z)
// Writes rh = r*hg into out_ht region, z into out_hnew region (temporaries).
__global__ __launch_bounds__(NTHREADS) void gru_phase1(
    const float* __restrict__ X, const float* __restrict__ h,
    const float* __restrict__ W_r, const float* __restrict__ W_z,
    const float* __restrict__ U_r, const float* __restrict__ U_z,
    const float* __restrict__ b_r, const float* __restrict__ b_z,
    float* __restrict__ out_hnew, float* __restrict__ out_ht)
{
    extern __shared__ float smem[];
    float* a_s  = smem;
    float* U_s  = smem + TB * D_SZ;
    float* w1_s = U_s + D_SZ * D_SZ;
    float* w2_s = w1_s + D_SZ;
    float* b1_s = w2_s + D_SZ;
    float* b2_s = b1_s + D_SZ;
    float* x_s  = b2_s + D_SZ;

    const int i   = blockIdx.y;
    const int b0  = blockIdx.x * TB;
    const int tid = threadIdx.x;

    // Load hg tile [TB][D]
    for (int t = tid; t < TB * D_SZ / 4; t += NTHREADS) {
        int row = t >> 5;   // 32 float4 per row
        int c4  = t & 31;
        ((float4*)a_s)[t] =
            ((const float4*)(h + (size_t)(b0 + row) * HD + (size_t)i * D_SZ))[c4];
    }
    // Load U_r
    {
        const float4* u4 = (const float4*)(U_r + (size_t)i * D_SZ * D_SZ);
        for (int t = tid; t < D_SZ * D_SZ / 4; t += NTHREADS)
            ((float4*)U_s)[t] = u4[t];
    }
    if (tid < D_SZ) {
        w1_s[tid] = W_r[i * D_SZ + tid];
        w2_s[tid] = W_z[i * D_SZ + tid];
        b1_s[tid] = b_r[i * D_SZ + tid];
        b2_s[tid] = b_z[i * D_SZ + tid];
    }
    if (tid < TB) x_s[tid] = X[(size_t)(b0 + tid) * I_SZ + i];
    __syncthreads();

    const int tc = tid & 15, trg = tid >> 4;
    const int r0 = trg * 4, c0 = tc * 8;

    float acc[4][8];
#pragma unroll
    for (int a = 0; a < 4; a++)
#pragma unroll
        for (int b = 0; b < 8; b++) acc[a][b] = 0.0f;

    GEMM_CORE(a_s, U_s, acc, r0, c0);
    __syncthreads();  // all threads done reading U_r before overwrite

    // Epilogue r -> write rh = r*hg into out_ht
#pragma unroll
    for (int rr = 0; rr < 4; rr++) {
        int row = r0 + rr;
        float xv = x_s[row];
        float o[8];
#pragma unroll
        for (int cc = 0; cc < 8; cc++) {
            int k = c0 + cc;
            float pre = acc[rr][cc] + xv * w1_s[k] + b1_s[k];
            float r = sigmoid_fast(pre);
            o[cc] = r * a_s[row * D_SZ + k];
        }
        float* dst = out_ht + (size_t)(b0 + row) * HD + (size_t)i * D_SZ + c0;
        ((float4*)dst)[0] = make_float4(o[0], o[1], o[2], o[3]);
        ((float4*)dst)[1] = make_float4(o[4], o[5], o[6], o[7]);
    }

    // Load U_z over U_s
    {
        const float4* u4 = (const float4*)(U_z + (size_t)i * D_SZ * D_SZ);
        for (int t = tid; t < D_SZ * D_SZ / 4; t += NTHREADS)
            ((float4*)U_s)[t] = u4[t];
    }
    __syncthreads();

#pragma unroll
    for (int a = 0; a < 4; a++)
#pragma unroll
        for (int b = 0; b < 8; b++) acc[a][b] = 0.0f;

    GEMM_CORE(a_s, U_s, acc, r0, c0);

    // Epilogue z -> write z into out_hnew (temporary storage)
#pragma unroll
    for (int rr = 0; rr < 4; rr++) {
        int row = r0 + rr;
        float xv = x_s[row];
        float o[8];
#pragma unroll
        for (int cc = 0; cc < 8; cc++) {
            int k = c0 + cc;
            float pre = acc[rr][cc] + xv * w2_s[k] + b2_s[k];
            o[cc] = sigmoid_fast(pre);
        }
        float* dst = out_hnew + (size_t)(b0 + row) * HD + (size_t)i * D_SZ + c0;
        ((float4*)dst)[0] = make_float4(o[0], o[1], o[2], o[3]);
        ((float4*)dst)[1] = make_float4(o[4], o[5], o[6], o[7]);
    }
}

// Phase 2: h_tilde = tanh(x*W_h + rh@U_h + b_h); h_new = z*hg + (1-z)*h_tilde.
// Reads rh from out_ht and z from out_hnew (rows owned by this block only),
// overwrites them with h_tilde / h_new in place.
__global__ __launch_bounds__(NTHREADS) void gru_phase2(
    const float* __restrict__ X, const float* __restrict__ h,
    const float* __restrict__ W_h, const float* __restrict__ U_h,
    const float* __restrict__ b_h,
    float* __restrict__ out_hnew, float* __restrict__ out_ht)
{
    extern __shared__ float smem[];
    float* a_s  = smem;                 // rh tile
    float* U_s  = smem + TB * D_SZ;
    float* w1_s = U_s + D_SZ * D_SZ;
    float* b1_s = w1_s + D_SZ;          // reuse slots; only need 2 small arrays
    float* x_s  = b1_s + D_SZ;

    const int i   = blockIdx.y;
    const int b0  = blockIdx.x * TB;
    const int tid = threadIdx.x;

    // Load rh tile from out_ht
    for (int t = tid; t < TB * D_SZ / 4; t += NTHREADS) {
        int row = t >> 5;
        int c4  = t & 31;
        ((float4*)a_s)[t] =
            ((const float4*)(out_ht + (size_t)(b0 + row) * HD + (size_t)i * D_SZ))[c4];
    }
    {
        const float4* u4 = (const float4*)(U_h + (size_t)i * D_SZ * D_SZ);
        for (int t = tid; t < D_SZ * D_SZ / 4; t += NTHREADS)
            ((float4*)U_s)[t] = u4[t];
    }
    if (tid < D_SZ) {
        w1_s[tid] = W_h[i * D_SZ + tid];
        b1_s[tid] = b_h[i * D_SZ + tid];
    }
    if (tid < TB) x_s[tid] = X[(size_t)(b0 + tid) * I_SZ + i];
    __syncthreads();

    const int tc = tid & 15, trg = tid >> 4;
    const int r0 = trg * 4, c0 = tc * 8;

    float acc[4][8];
#pragma unroll
    for (int a = 0; a < 4; a++)
#pragma unroll
        for (int b = 0; b < 8; b++) acc[a][b] = 0.0f;

    GEMM_CORE(a_s, U_s, acc, r0, c0);

    // Fused epilogue: h_tilde + final gate combine
#pragma unroll
    for (int rr = 0; rr < 4; rr++) {
        int row = r0 + rr;
        float xv = x_s[row];
        size_t gbase = (size_t)(b0 + row) * HD + (size_t)i * D_SZ + c0;

        float4 z1 = ((const float4*)(out_hnew + gbase))[0];
        float4 z2 = ((const float4*)(out_hnew + gbase))[1];
        float4 g1 = ((const float4*)(h + gbase))[0];
        float4 g2 = ((const float4*)(h + gbase))[1];
        float zv[8] = {z1.x, z1.y, z1.z, z1.w, z2.x, z2.y, z2.z, z2.w};
        float gv[8] = {g1.x, g1.y, g1.z, g1.w, g2.x, g2.y, g2.z, g2.w};

        float ht[8], hn[8];
#pragma unroll
        for (int cc = 0; cc < 8; cc++) {
            int k = c0 + cc;
            float pre = acc[rr][cc] + xv * w1_s[k] + b1_s[k];
            float t = tanhf(pre);
            ht[cc] = t;
            hn[cc] = zv[cc] * gv[cc] + (1.0f - zv[cc]) * t;
        }
        ((float4*)(out_ht + gbase))[0]   = make_float4(ht[0], ht[1], ht[2], ht[3]);
        ((float4*)(out_ht + gbase))[1]   = make_float4(ht[4], ht[5], ht[6], ht[7]);
        ((float4*)(out_hnew + gbase))[0] = make_float4(hn[0], hn[1], hn[2], hn[3]);
        ((float4*)(out_hnew + gbase))[1] = make_float4(hn[4], hn[5], hn[6], hn[7]);
    }
}

extern "C" void kernel_launch(void* const* d_in, const int* in_sizes, int n_in,
                              void* d_out, int out_size) {
    const float* X  = (const float*)d_in[0];
    const float* h  = (const float*)d_in[1];
    const float* Wr = (const float*)d_in[2];
    const float* Wz = (const float*)d_in[3];
    const float* Wh = (const float*)d_in[4];
    const float* Ur = (const float*)d_in[5];
    const float* Uz = (const float*)d_in[6];
    const float* Uh = (const float*)d_in[7];
    const float* br = (const float*)d_in[8];
    const float* bz = (const float*)d_in[9];
    const float* bh = (const float*)d_in[10];

    float* out      = (float*)d_out;
    float* out_hnew = out;                           // first output of tuple
    float* out_ht   = out + (size_t)B_SZ * HD;       // second output of tuple

    cudaFuncSetAttribute(gru_phase1, cudaFuncAttributeMaxDynamicSharedMemorySize,
                         (int)SMEM_BYTES);
    cudaFuncSetAttribute(gru_phase2, cudaFuncAttributeMaxDynamicSharedMemorySize,
                         (int)SMEM_BYTES);

    dim3 grid(B_SZ / TB, I_SZ);  // x = batch tile (fast) -> U reuse in L2 across a wave
    gru_phase1<<<grid, NTHREADS, SMEM_BYTES>>>(X, h, Wr, Wz, Ur, Uz, br, bz,
                                               out_hnew, out_ht);
    gru_phase2<<<grid, NTHREADS, SMEM_BYTES>>>(X, h, Wh, Uh, bh, out_hnew, out_ht);
}

// round 4
// speedup vs baseline: 2.7391x; 2.7391x over previous
#include <cuda_runtime.h>
#include <cuda_fp16.h>
#include <stdint.h>
#include <math.h>

constexpr int I_SZ = 256, D_SZ = 128, HD = 32768, MB = 128;
constexpr int ROWB = 272;                 // padded row: 136 halfs = 272 B (17*16B)
constexpr uint32_t PLANE = 128 * ROWB;    // 34816 B per [128][136] fp16 plane
constexpr uint32_t SM_AH = 0;
constexpr uint32_t SM_AL = PLANE;
constexpr uint32_t SM_U0 = 2 * PLANE;     // hi plane; lo at +PLANE
constexpr uint32_t SM_U1 = 4 * PLANE;
constexpr uint32_t SM_WB = 6 * PLANE;     // 6*128 floats
constexpr uint32_t SM_X  = SM_WB + 3072;  // 128 floats
constexpr uint32_t SMEM_MAIN = SM_X + 512;  // 212480 B

// U scratch: [gate z/r/h][group] -> 64KB: hi[128][128] fp16 then lo[128][128]
__device__ __align__(256) unsigned char g_Uscr[3ull * 256 * 65536];

__device__ __forceinline__ uint32_t smem_u32(const void* p) {
    uint32_t a;
    asm("{ .reg .u64 t; cvta.to.shared.u64 t, %1; cvt.u32.u64 %0, t; }" : "=r"(a) : "l"(p));
    return a;
}
#define CP16(dst, src) asm volatile("cp.async.cg.shared.global [%0], [%1], 16;" :: "r"(dst), "l"(src))
#define CP_COMMIT()    asm volatile("cp.async.commit_group;" ::: "memory")
#define CP_WAIT(n)     asm volatile("cp.async.wait_group %0;" :: "n"(n) : "memory")
#define LDSM4(R, addr)                                                          \
    asm volatile("ldmatrix.sync.aligned.m8n8.x4.shared.b16 {%0,%1,%2,%3}, [%4];"\
        : "=r"((R)[0]), "=r"((R)[1]), "=r"((R)[2]), "=r"((R)[3]) : "r"(addr))
#define MMA16816(c, a0, a1, a2, a3, b0, b1)                                     \
    asm volatile("mma.sync.aligned.m16n8k16.row.col.f32.f16.f16.f32 "           \
        "{%0,%1,%2,%3}, {%4,%5,%6,%7}, {%8,%9}, {%0,%1,%2,%3};"                 \
        : "+f"((c)[0]), "+f"((c)[1]), "+f"((c)[2]), "+f"((c)[3])                \
        : "r"(a0), "r"(a1), "r"(a2), "r"(a3), "r"(b0), "r"(b1))

__device__ __forceinline__ float sigf(float x) { return 1.0f / (1.0f + __expf(-x)); }

__device__ __forceinline__ void split8h(const float* v, uint4& hi, uint4& lo) {
    uint32_t hw[4], lw[4];
#pragma unroll
    for (int j = 0; j < 4; j++) {
        __half h0 = __float2half_rn(v[2 * j]), h1 = __float2half_rn(v[2 * j + 1]);
        __half l0 = __float2half_rn(v[2 * j] - __half2float(h0));
        __half l1 = __float2half_rn(v[2 * j + 1] - __half2float(h1));
        hw[j] = (uint32_t)__half_as_ushort(h0) | ((uint32_t)__half_as_ushort(h1) << 16);
        lw[j] = (uint32_t)__half_as_ushort(l0) | ((uint32_t)__half_as_ushort(l1) << 16);
    }
    hi = make_uint4(hw[0], hw[1], hw[2], hw[3]);
    lo = make_uint4(lw[0], lw[1], lw[2], lw[3]);
}

// ---------- prep: U[i][k][n] -> B[n][k] fp16 hi/lo planes ----------
__global__ __launch_bounds__(256) void gru_prep(const float* __restrict__ Uz,
                                                const float* __restrict__ Ur,
                                                const float* __restrict__ Uh) {
    extern __shared__ float sf[];  // [128][129]
    const int i = blockIdx.x, g = blockIdx.y, tid = threadIdx.x;
    const float* Ui = ((g == 0) ? Uz : (g == 1) ? Ur : Uh) + (size_t)i * D_SZ * D_SZ;
    for (int t = tid; t < D_SZ * D_SZ; t += 256) sf[(t >> 7) * 129 + (t & 127)] = Ui[t];
    __syncthreads();
    unsigned char* hp = g_Uscr + (size_t)(g * 256 + i) * 65536;
    unsigned char* lp = hp + 32768;
    for (int c = tid; c < 2048; c += 256) {
        int n = c >> 4, k0 = (c & 15) * 8;
        float v[8];
#pragma unroll
        for (int j = 0; j < 8; j++) v[j] = sf[(k0 + j) * 129 + n];  // B[n][k] = U[k][n]
        uint4 hi, lo;
        split8h(v, hi, lo);
        *(uint4*)(hp + n * 256 + k0 * 2) = hi;
        *(uint4*)(lp + n * 256 + k0 * 2) = lo;
    }
}

// cp.async one U gate (64KB) into a smem double-buffer slot
__device__ __forceinline__ void cp_u(uint32_t dst, const unsigned char* src, int tid) {
#pragma unroll
    for (int t = tid; t < 4096; t += 256) {
        uint32_t plane = t >> 11, rem = t & 2047, row = rem >> 4, c = rem & 15;
        CP16(dst + plane * PLANE + row * ROWB + c * 16, src + (size_t)t * 16);
    }
    CP_COMMIT();
}

// 3-split GEMM: acc += AH*UH + AH*UL + AL*UH   (M=32, N=64 warp tile, K=128)
__device__ __forceinline__ void gemm3(uint32_t sb, uint32_t ub, int warp_m, int warp_n,
                                      uint32_t offA, uint32_t offB, float acc[2][8][4]) {
#pragma unroll
    for (int mi = 0; mi < 2; mi++)
#pragma unroll
        for (int ni = 0; ni < 8; ni++)
#pragma unroll
            for (int q = 0; q < 4; q++) acc[mi][ni][q] = 0.0f;
#pragma unroll
    for (int ks = 0; ks < 8; ks++) {
        const uint32_t kb = ks * 32;
        uint32_t AH[2][4], AL[2][4], BH[4][4], BL[4][4];
#pragma unroll
        for (int mi = 0; mi < 2; mi++) {
            uint32_t a = sb + SM_AH + (warp_m + mi * 16) * ROWB + kb + offA;
            LDSM4(AH[mi], a);
            LDSM4(AL[mi], a + PLANE);
        }
#pragma unroll
        for (int nj = 0; nj < 4; nj++) {
            uint32_t b = ub + (warp_n + nj * 16) * ROWB + kb + offB;
            LDSM4(BH[nj], b);
            LDSM4(BL[nj], b + PLANE);
        }
#pragma unroll
        for (int mi = 0; mi < 2; mi++)
#pragma unroll
            for (int nj = 0; nj < 4; nj++)
#pragma unroll
                for (int hh = 0; hh < 2; hh++) {
                    float* c = acc[mi][nj * 2 + hh];
                    uint32_t b0h = BH[nj][hh * 2], b1h = BH[nj][hh * 2 + 1];
                    uint32_t b0l = BL[nj][hh * 2], b1l = BL[nj][hh * 2 + 1];
                    MMA16816(c, AH[mi][0], AH[mi][1], AH[mi][2], AH[mi][3], b0h, b1h);
                    MMA16816(c, AH[mi][0], AH[mi][1], AH[mi][2], AH[mi][3], b0l, b1l);
                    MMA16816(c, AL[mi][0], AL[mi][1], AL[mi][2], AL[mi][3], b0h, b1h);
                }
    }
}

// ---------- main fused kernel ----------
__global__ __launch_bounds__(256, 1) void gru_main(
    const float* __restrict__ X, const float* __restrict__ hs,
    const float* __restrict__ Wr, const float* __restrict__ Wz, const float* __restrict__ Wh,
    const float* __restrict__ br, const float* __restrict__ bz, const float* __restrict__ bh,
    float* __restrict__ out_hnew, float* __restrict__ out_ht) {
    extern __shared__ __align__(16) unsigned char smem[];
    const uint32_t sb = smem_u32(smem);
    const int tid = threadIdx.x, warp = tid >> 5, l = tid & 31;
    const int i = blockIdx.y, b0 = blockIdx.x * MB;

    float* wb  = (float*)(smem + SM_WB);  // wz|bz|wr|br|wh|bh
    float* x_s = (float*)(smem + SM_X);

    const unsigned char* uz = g_Uscr + (size_t)(0 * 256 + i) * 65536;
    const unsigned char* ur = g_Uscr + (size_t)(1 * 256 + i) * 65536;
    const unsigned char* uh = g_Uscr + (size_t)(2 * 256 + i) * 65536;
    cp_u(sb + SM_U0, uz, tid);   // group 1
    cp_u(sb + SM_U1, ur, tid);   // group 2

    if (tid < 128) {
        wb[tid]       = Wz[i * D_SZ + tid];
        wb[128 + tid] = bz[i * D_SZ + tid];
        wb[256 + tid] = Wr[i * D_SZ + tid];
        wb[384 + tid] = br[i * D_SZ + tid];
        wb[512 + tid] = Wh[i * D_SZ + tid];
        wb[640 + tid] = bh[i * D_SZ + tid];
        x_s[tid] = X[(size_t)(b0 + tid) * I_SZ + i];
    }
    // A <= split(hg)
    for (int c = tid; c < 2048; c += 256) {
        int row = c >> 4, k0 = (c & 15) * 8;
        const float4* g = (const float4*)(hs + (size_t)(b0 + row) * HD + (size_t)i * D_SZ + k0);
        float4 v0 = g[0], v1 = g[1];
        float v[8] = {v0.x, v0.y, v0.z, v0.w, v1.x, v1.y, v1.z, v1.w};
        uint4 hi, lo;
        split8h(v, hi, lo);
        *(uint4*)(smem + SM_AH + row * ROWB + k0 * 2) = hi;
        *(uint4*)(smem + SM_AL + row * ROWB + k0 * 2) = lo;
    }
    CP_WAIT(1);          // Uz resident
    __syncthreads();

    const int warp_m = (warp & 3) * 32, warp_n = (warp >> 2) * 64;
    const uint32_t offA = (uint32_t)((l & 15) * ROWB + (l >> 4) * 16);
    const uint32_t offB = (uint32_t)((l & 7) * ROWB + ((l >> 4) & 1) * (8 * ROWB) +
                                     ((l >> 3) & 1) * 16);
    float acc[2][8][4], z[2][8][4];

    // ---- z gate ----
    gemm3(sb, sb + SM_U0, warp_m, warp_n, offA, offB, acc);
#pragma unroll
    for (int mi = 0; mi < 2; mi++)
#pragma unroll
        for (int ni = 0; ni < 8; ni++) {
            int col = warp_n + ni * 8 + (l & 3) * 2;
            float w0 = wb[col], w1 = wb[col + 1], c0 = wb[128 + col], c1 = wb[129 + col];
#pragma unroll
            for (int rr = 0; rr < 2; rr++) {
                int row = warp_m + mi * 16 + rr * 8 + (l >> 2);
                float xv = x_s[row];
                z[mi][ni][rr * 2]     = sigf(acc[mi][ni][rr * 2] + xv * w0 + c0);
                z[mi][ni][rr * 2 + 1] = sigf(acc[mi][ni][rr * 2 + 1] + xv * w1 + c1);
            }
        }
    __syncthreads();             // all warps done reading U0
    cp_u(sb + SM_U0, uh, tid);   // group 3: Uh -> U0 (overlaps r gemm)
    CP_WAIT(1);                  // Ur resident
    __syncthreads();

    // ---- r gate ----
    gemm3(sb, sb + SM_U1, warp_m, warp_n, offA, offB, acc);
    __syncthreads();             // all warps done reading A planes
    // r epilogue: hg = AH+AL (exact to 2^-22), A <= split(r*hg)
#pragma unroll
    for (int mi = 0; mi < 2; mi++)
#pragma unroll
        for (int ni = 0; ni < 8; ni++) {
            int col = warp_n + ni * 8 + (l & 3) * 2;
            float w0 = wb[256 + col], w1 = wb[257 + col];
            float c0 = wb[384 + col], c1 = wb[385 + col];
#pragma unroll
            for (int rr = 0; rr < 2; rr++) {
                int row = warp_m + mi * 16 + rr * 8 + (l >> 2);
                float xv = x_s[row];
                half2* pH = (half2*)(smem + SM_AH + row * ROWB + col * 2);
                half2* pL = (half2*)(smem + SM_AL + row * ROWB + col * 2);
                half2 hh = *pH, ll = *pL;
                float hg0 = __half2float(__low2half(hh)) + __half2float(__low2half(ll));
                float hg1 = __half2float(__high2half(hh)) + __half2float(__high2half(ll));
                float r0 = sigf(acc[mi][ni][rr * 2] + xv * w0 + c0);
                float r1 = sigf(acc[mi][ni][rr * 2 + 1] + xv * w1 + c1);
                float rh0 = r0 * hg0, rh1 = r1 * hg1;
                __half h0 = __float2half_rn(rh0), h1 = __float2half_rn(rh1);
                *pH = __halves2half2(h0, h1);
                *pL = __halves2half2(__float2half_rn(rh0 - __half2float(h0)),
                                     __float2half_rn(rh1 - __half2float(h1)));
            }
        }
    CP_WAIT(0);                  // Uh resident
    __syncthreads();             // rh planes visible to all

    // ---- h gate + fused combine ----
    gemm3(sb, sb + SM_U0, warp_m, warp_n, offA, offB, acc);
#pragma unroll
    for (int mi = 0; mi < 2; mi++)
#pragma unroll
        for (int ni = 0; ni < 8; ni++) {
            int col = warp_n + ni * 8 + (l & 3) * 2;
            float w0 = wb[512 + col], w1 = wb[513 + col];
            float c0 = wb[640 + col], c1 = wb[641 + col];
#pragma unroll
            for (int rr = 0; rr < 2; rr++) {
                int row = warp_m + mi * 16 + rr * 8 + (l >> 2);
                float xv = x_s[row];
                size_t gidx = (size_t)(b0 + row) * HD + (size_t)i * D_SZ + col;
                float2 hg = *(const float2*)(hs + gidx);
                float t0 = tanhf(acc[mi][ni][rr * 2] + xv * w0 + c0);
                float t1 = tanhf(acc[mi][ni][rr * 2 + 1] + xv * w1 + c1);
                float z0 = z[mi][ni][rr * 2], z1 = z[mi][ni][rr * 2 + 1];
                float2 ht2 = make_float2(t0, t1);
                float2 hn2 = make_float2(z0 * hg.x + (1.0f - z0) * t0,
                                         z1 * hg.y + (1.0f - z1) * t1);
                *(float2*)(out_ht + gidx)   = ht2;
                *(float2*)(out_hnew + gidx) = hn2;
            }
        }
}

extern "C" void kernel_launch(void* const* d_in, const int* in_sizes, int n_in,
                              void* d_out, int out_size) {
    const float* X  = (const float*)d_in[0];
    const float* h  = (const float*)d_in[1];
    const float* Wr = (const float*)d_in[2];
    const float* Wz = (const float*)d_in[3];
    const float* Wh = (const float*)d_in[4];
    const float* Ur = (const float*)d_in[5];
    const float* Uz = (const float*)d_in[6];
    const float* Uh = (const float*)d_in[7];
    const float* br = (const float*)d_in[8];
    const float* bz = (const float*)d_in[9];
    const float* bh = (const float*)d_in[10];
    float* out = (float*)d_out;
    float* out_hnew = out;
    float* out_ht   = out + (size_t)1024 * HD;

    cudaFuncSetAttribute(gru_prep, cudaFuncAttributeMaxDynamicSharedMemorySize, 128 * 129 * 4);
    cudaFuncSetAttribute(gru_main, cudaFuncAttributeMaxDynamicSharedMemorySize, (int)SMEM_MAIN);

    gru_prep<<<dim3(256, 3), 256, 128 * 129 * 4>>>(Uz, Ur, Uh);
    gru_main<<<dim3(8, 256), 256, SMEM_MAIN>>>(X, h, Wr, Wz, Wh, br, bz, bh,
                                               out_hnew, out_ht);
}

// round 5
// speedup vs baseline: 3.4809x; 1.2708x over previous
#include <cuda_runtime.h>
#include <cuda_fp16.h>
#include <stdint.h>
#include <math.h>

constexpr int I_SZ = 256, D_SZ = 128, HD = 32768, MB = 64;
constexpr int ROWB = 272;                    // padded row: 136 halfs = 272 B
constexpr uint32_t A_PLANE = 64 * ROWB;      // 17408 B  [64][136] fp16
constexpr uint32_t U_PLANE = 128 * ROWB;     // 34816 B  [128][136] fp16
constexpr uint32_t SM_AH = 0;
constexpr uint32_t SM_AL = A_PLANE;
constexpr uint32_t SM_U  = 2 * A_PLANE;      // hi plane; lo at +U_PLANE
constexpr uint32_t SM_WB = SM_U + 2 * U_PLANE;   // 104448; 6*128 floats
constexpr uint32_t SM_X  = SM_WB + 3072;         // 128 floats
constexpr uint32_t SMEM_MAIN = SM_X + 512;       // 108032 B -> 2 CTAs/SM

// U scratch: [gate z/r/h][group] -> 64KB: hi[128][128] fp16 then lo[128][128]
__device__ __align__(256) unsigned char g_Uscr[3ull * 256 * 65536];

__device__ __forceinline__ uint32_t smem_u32(const void* p) {
    uint32_t a;
    asm("{ .reg .u64 t; cvta.to.shared.u64 t, %1; cvt.u32.u64 %0, t; }" : "=r"(a) : "l"(p));
    return a;
}
#define CP16(dst, src) asm volatile("cp.async.cg.shared.global [%0], [%1], 16;" :: "r"(dst), "l"(src))
#define CP_COMMIT()    asm volatile("cp.async.commit_group;" ::: "memory")
#define CP_WAIT(n)     asm volatile("cp.async.wait_group %0;" :: "n"(n) : "memory")
#define LDSM4(R, addr)                                                          \
    asm volatile("ldmatrix.sync.aligned.m8n8.x4.shared.b16 {%0,%1,%2,%3}, [%4];"\
        : "=r"((R)[0]), "=r"((R)[1]), "=r"((R)[2]), "=r"((R)[3]) : "r"(addr))
#define MMA16816(c, a0, a1, a2, a3, b0, b1)                                     \
    asm volatile("mma.sync.aligned.m16n8k16.row.col.f32.f16.f16.f32 "           \
        "{%0,%1,%2,%3}, {%4,%5,%6,%7}, {%8,%9}, {%0,%1,%2,%3};"                 \
        : "+f"((c)[0]), "+f"((c)[1]), "+f"((c)[2]), "+f"((c)[3])                \
        : "r"(a0), "r"(a1), "r"(a2), "r"(a3), "r"(b0), "r"(b1))

__device__ __forceinline__ float sigf(float x) { return 1.0f / (1.0f + __expf(-x)); }
__device__ __forceinline__ float tanhfast(float x) {
    return 2.0f / (1.0f + __expf(-2.0f * x)) - 1.0f;
}

__device__ __forceinline__ void split8h(const float* v, uint4& hi, uint4& lo) {
    uint32_t hw[4], lw[4];
#pragma unroll
    for (int j = 0; j < 4; j++) {
        __half h0 = __float2half_rn(v[2 * j]), h1 = __float2half_rn(v[2 * j + 1]);
        __half l0 = __float2half_rn(v[2 * j] - __half2float(h0));
        __half l1 = __float2half_rn(v[2 * j + 1] - __half2float(h1));
        hw[j] = (uint32_t)__half_as_ushort(h0) | ((uint32_t)__half_as_ushort(h1) << 16);
        lw[j] = (uint32_t)__half_as_ushort(l0) | ((uint32_t)__half_as_ushort(l1) << 16);
    }
    hi = make_uint4(hw[0], hw[1], hw[2], hw[3]);
    lo = make_uint4(lw[0], lw[1], lw[2], lw[3]);
}

// ---------- prep: U[i][k][n] -> B[n][k] fp16 hi/lo planes ----------
__global__ __launch_bounds__(256) void gru_prep(const float* __restrict__ Uz,
                                                const float* __restrict__ Ur,
                                                const float* __restrict__ Uh) {
    extern __shared__ float sf[];  // [128][129]
    const int i = blockIdx.x, g = blockIdx.y, tid = threadIdx.x;
    const float* Ui = ((g == 0) ? Uz : (g == 1) ? Ur : Uh) + (size_t)i * D_SZ * D_SZ;
    for (int t = tid; t < D_SZ * D_SZ; t += 256) sf[(t >> 7) * 129 + (t & 127)] = Ui[t];
    __syncthreads();
    unsigned char* hp = g_Uscr + (size_t)(g * 256 + i) * 65536;
    unsigned char* lp = hp + 32768;
    for (int c = tid; c < 2048; c += 256) {
        int n = c >> 4, k0 = (c & 15) * 8;
        float v[8];
#pragma unroll
        for (int j = 0; j < 8; j++) v[j] = sf[(k0 + j) * 129 + n];  // B[n][k] = U[k][n]
        uint4 hi, lo;
        split8h(v, hi, lo);
        *(uint4*)(hp + n * 256 + k0 * 2) = hi;
        *(uint4*)(lp + n * 256 + k0 * 2) = lo;
    }
}

// cp.async one U gate (hi+lo 64KB src) into the single smem U buffer
__device__ __forceinline__ void cp_u(uint32_t dst, const unsigned char* src, int tid) {
#pragma unroll
    for (int t = tid; t < 4096; t += 256) {
        uint32_t plane = t >> 11, rem = t & 2047, row = rem >> 4, c = rem & 15;
        CP16(dst + plane * U_PLANE + row * ROWB + c * 16, src + (size_t)t * 16);
    }
    CP_COMMIT();
}

// 3-split GEMM: acc += AH*UH + AH*UL + AL*UH   (warp tile M=32, N=32, K=128)
__device__ __forceinline__ void gemm3(uint32_t sb, uint32_t ub, int warp_m, int warp_n,
                                      uint32_t offA, uint32_t offB, float acc[2][4][4]) {
#pragma unroll
    for (int mi = 0; mi < 2; mi++)
#pragma unroll
        for (int ni = 0; ni < 4; ni++)
#pragma unroll
            for (int q = 0; q < 4; q++) acc[mi][ni][q] = 0.0f;
#pragma unroll
    for (int ks = 0; ks < 8; ks++) {
        const uint32_t kb = ks * 32;
        uint32_t AH[2][4], AL[2][4], BH[2][4], BL[2][4];
#pragma unroll
        for (int mi = 0; mi < 2; mi++) {
            uint32_t a = sb + SM_AH + (warp_m + mi * 16) * ROWB + kb + offA;
            LDSM4(AH[mi], a);
            LDSM4(AL[mi], a + A_PLANE);
        }
#pragma unroll
        for (int nj = 0; nj < 2; nj++) {
            uint32_t b = ub + (warp_n + nj * 16) * ROWB + kb + offB;
            LDSM4(BH[nj], b);
            LDSM4(BL[nj], b + U_PLANE);
        }
#pragma unroll
        for (int mi = 0; mi < 2; mi++)
#pragma unroll
            for (int nj = 0; nj < 2; nj++)
#pragma unroll
                for (int hh = 0; hh < 2; hh++) {
                    float* c = acc[mi][nj * 2 + hh];
                    uint32_t b0h = BH[nj][hh * 2], b1h = BH[nj][hh * 2 + 1];
                    uint32_t b0l = BL[nj][hh * 2], b1l = BL[nj][hh * 2 + 1];
                    MMA16816(c, AH[mi][0], AH[mi][1], AH[mi][2], AH[mi][3], b0h, b1h);
                    MMA16816(c, AH[mi][0], AH[mi][1], AH[mi][2], AH[mi][3], b0l, b1l);
                    MMA16816(c, AL[mi][0], AL[mi][1], AL[mi][2], AL[mi][3], b0h, b1h);
                }
    }
}

// ---------- main fused kernel: M=64 rows/CTA, 2 CTAs/SM ----------
__global__ __launch_bounds__(256, 2) void gru_main(
    const float* __restrict__ X, const float* __restrict__ hs,
    const float* __restrict__ Wr, const float* __restrict__ Wz, const float* __restrict__ Wh,
    const float* __restrict__ br, const float* __restrict__ bz, const float* __restrict__ bh,
    float* __restrict__ out_hnew, float* __restrict__ out_ht) {
    extern __shared__ __align__(16) unsigned char smem[];
    const uint32_t sb = smem_u32(smem);
    const int tid = threadIdx.x, warp = tid >> 5, l = tid & 31;
    const int i = blockIdx.y, b0 = blockIdx.x * MB;

    float* wb  = (float*)(smem + SM_WB);  // wz|bz|wr|br|wh|bh
    float* x_s = (float*)(smem + SM_X);

    const unsigned char* uz = g_Uscr + (size_t)(0 * 256 + i) * 65536;
    const unsigned char* ur = g_Uscr + (size_t)(1 * 256 + i) * 65536;
    const unsigned char* uh = g_Uscr + (size_t)(2 * 256 + i) * 65536;
    cp_u(sb + SM_U, uz, tid);

    if (tid < 128) {
        wb[tid]       = Wz[i * D_SZ + tid];
        wb[128 + tid] = bz[i * D_SZ + tid];
        wb[256 + tid] = Wr[i * D_SZ + tid];
        wb[384 + tid] = br[i * D_SZ + tid];
        wb[512 + tid] = Wh[i * D_SZ + tid];
        wb[640 + tid] = bh[i * D_SZ + tid];
    }
    if (tid < MB) x_s[tid] = X[(size_t)(b0 + tid) * I_SZ + i];

    // A <= split(hg)  (64 rows x 16 col-chunks)
    for (int c = tid; c < 1024; c += 256) {
        int row = c >> 4, k0 = (c & 15) * 8;
        const float4* g = (const float4*)(hs + (size_t)(b0 + row) * HD + (size_t)i * D_SZ + k0);
        float4 v0 = g[0], v1 = g[1];
        float v[8] = {v0.x, v0.y, v0.z, v0.w, v1.x, v1.y, v1.z, v1.w};
        uint4 hi, lo;
        split8h(v, hi, lo);
        *(uint4*)(smem + SM_AH + row * ROWB + k0 * 2) = hi;
        *(uint4*)(smem + SM_AL + row * ROWB + k0 * 2) = lo;
    }
    CP_WAIT(0);
    __syncthreads();

    const int warp_m = (warp & 1) * 32, warp_n = (warp >> 1) * 32;
    const uint32_t offA = (uint32_t)((l & 15) * ROWB + (l >> 4) * 16);
    const uint32_t offB = (uint32_t)((l & 7) * ROWB + ((l >> 4) & 1) * (8 * ROWB) +
                                     ((l >> 3) & 1) * 16);
    float acc[2][4][4], z[2][4][4];

    // ---- z gate ----
    gemm3(sb, sb + SM_U, warp_m, warp_n, offA, offB, acc);
#pragma unroll
    for (int mi = 0; mi < 2; mi++)
#pragma unroll
        for (int ni = 0; ni < 4; ni++) {
            int col = warp_n + ni * 8 + (l & 3) * 2;
            float w0 = wb[col], w1 = wb[col + 1], c0 = wb[128 + col], c1 = wb[129 + col];
#pragma unroll
            for (int rr = 0; rr < 2; rr++) {
                int row = warp_m + mi * 16 + rr * 8 + (l >> 2);
                float xv = x_s[row];
                z[mi][ni][rr * 2]     = sigf(acc[mi][ni][rr * 2] + xv * w0 + c0);
                z[mi][ni][rr * 2 + 1] = sigf(acc[mi][ni][rr * 2 + 1] + xv * w1 + c1);
            }
        }
    __syncthreads();             // all warps done reading Uz
    cp_u(sb + SM_U, ur, tid);
    CP_WAIT(0);
    __syncthreads();             // Ur resident

    // ---- r gate ----
    gemm3(sb, sb + SM_U, warp_m, warp_n, offA, offB, acc);
    __syncthreads();             // all warps done reading A planes + Ur
    cp_u(sb + SM_U, uh, tid);    // Uh load overlaps r-epilogue

    // r epilogue: hg = AH+AL (exact), A <= split(r*hg) in place
#pragma unroll
    for (int mi = 0; mi < 2; mi++)
#pragma unroll
        for (int ni = 0; ni < 4; ni++) {
            int col = warp_n + ni * 8 + (l & 3) * 2;
            float w0 = wb[256 + col], w1 = wb[257 + col];
            float c0 = wb[384 + col], c1 = wb[385 + col];
#pragma unroll
            for (int rr = 0; rr < 2; rr++) {
                int row = warp_m + mi * 16 + rr * 8 + (l >> 2);
                float xv = x_s[row];
                half2* pH = (half2*)(smem + SM_AH + row * ROWB + col * 2);
                half2* pL = (half2*)(smem + SM_AL + row * ROWB + col * 2);
                half2 hh = *pH, ll = *pL;
                float hg0 = __half2float(__low2half(hh)) + __half2float(__low2half(ll));
                float hg1 = __half2float(__high2half(hh)) + __half2float(__high2half(ll));
                float r0 = sigf(acc[mi][ni][rr * 2] + xv * w0 + c0);
                float r1 = sigf(acc[mi][ni][rr * 2 + 1] + xv * w1 + c1);
                float rh0 = r0 * hg0, rh1 = r1 * hg1;
                __half h0 = __float2half_rn(rh0), h1 = __float2half_rn(rh1);
                *pH = __halves2half2(h0, h1);
                *pL = __halves2half2(__float2half_rn(rh0 - __half2float(h0)),
                                     __float2half_rn(rh1 - __half2float(h1)));
            }
        }
    CP_WAIT(0);
    __syncthreads();             // Uh resident + rh planes visible

    // ---- h gate + fused combine ----
    gemm3(sb, sb + SM_U, warp_m, warp_n, offA, offB, acc);
#pragma unroll
    for (int mi = 0; mi < 2; mi++)
#pragma unroll
        for (int ni = 0; ni < 4; ni++) {
            int col = warp_n + ni * 8 + (l & 3) * 2;
            float w0 = wb[512 + col], w1 = wb[513 + col];
            float c0 = wb[640 + col], c1 = wb[641 + col];
#pragma unroll
            for (int rr = 0; rr < 2; rr++) {
                int row = warp_m + mi * 16 + rr * 8 + (l >> 2);
                float xv = x_s[row];
                size_t gidx = (size_t)(b0 + row) * HD + (size_t)i * D_SZ + col;
                float2 hg = *(const float2*)(hs + gidx);
                float t0 = tanhfast(acc[mi][ni][rr * 2] + xv * w0 + c0);
                float t1 = tanhfast(acc[mi][ni][rr * 2 + 1] + xv * w1 + c1);
                float z0 = z[mi][ni][rr * 2], z1 = z[mi][ni][rr * 2 + 1];
                *(float2*)(out_ht + gidx)   = make_float2(t0, t1);
                *(float2*)(out_hnew + gidx) = make_float2(z0 * hg.x + (1.0f - z0) * t0,
                                                          z1 * hg.y + (1.0f - z1) * t1);
            }
        }
}

extern "C" void kernel_launch(void* const* d_in, const int* in_sizes, int n_in,
                              void* d_out, int out_size) {
    const float* X  = (const float*)d_in[0];
    const float* h  = (const float*)d_in[1];
    const float* Wr = (const float*)d_in[2];
    const float* Wz = (const float*)d_in[3];
    const float* Wh = (const float*)d_in[4];
    const float* Ur = (const float*)d_in[5];
    const float* Uz = (const float*)d_in[6];
    const float* Uh = (const float*)d_in[7];
    const float* br = (const float*)d_in[8];
    const float* bz = (const float*)d_in[9];
    const float* bh = (const float*)d_in[10];
    float* out = (float*)d_out;
    float* out_hnew = out;
    float* out_ht   = out + (size_t)1024 * HD;

    cudaFuncSetAttribute(gru_prep, cudaFuncAttributeMaxDynamicSharedMemorySize, 128 * 129 * 4);
    cudaFuncSetAttribute(gru_main, cudaFuncAttributeMaxDynamicSharedMemorySize, (int)SMEM_MAIN);

    gru_prep<<<dim3(256, 3), 256, 128 * 129 * 4>>>(Uz, Ur, Uh);
    gru_main<<<dim3(16, 256), 256, SMEM_MAIN>>>(X, h, Wr, Wz, Wh, br, bz, bh,
                                                out_hnew, out_ht);
}

// round 7
// speedup vs baseline: 4.2570x; 1.2230x over previous
#include <cuda_runtime.h>
#include <cuda_fp16.h>
#include <stdint.h>
#include <math.h>

constexpr int I_SZ = 256, D_SZ = 128, HD = 32768, MB = 64;
constexpr int ROWB = 272;                    // padded row: 136 halfs = 272 B
constexpr uint32_t A_PLANE = 64 * ROWB;      // 17408 B  [64][136] fp16
constexpr uint32_t U_PLANE = 128 * ROWB;     // 34816 B  [128][136] fp16
constexpr uint32_t SM_AH = 0;
constexpr uint32_t SM_AL = A_PLANE;
constexpr uint32_t SM_U0 = 2 * A_PLANE;          // 34816
constexpr uint32_t SM_U1 = SM_U0 + U_PLANE;      // 69632
constexpr uint32_t SM_WB = SM_U1 + U_PLANE;      // 104448; 6*128 floats
constexpr uint32_t SM_X  = SM_WB + 3072;
constexpr uint32_t SMEM_MAIN = SM_X + 512;       // 108032 B -> 2 CTAs/SM

// U scratch: [gate z/r/h][group] -> 32KB fp16 [n=128][k=128]
__device__ __align__(256) unsigned char g_Uscr[3ull * 256 * 32768];

__device__ __forceinline__ uint32_t smem_u32(const void* p) {
    uint32_t a;
    asm("{ .reg .u64 t; cvta.to.shared.u64 t, %1; cvt.u32.u64 %0, t; }" : "=r"(a) : "l"(p));
    return a;
}
#define CP16(dst, src) asm volatile("cp.async.cg.shared.global [%0], [%1], 16;" :: "r"(dst), "l"(src))
#define CP_COMMIT()    asm volatile("cp.async.commit_group;" ::: "memory")
#define CP_WAIT(n)     asm volatile("cp.async.wait_group %0;" :: "n"(n) : "memory")
#define LDSM4(R, addr)                                                          \
    asm volatile("ldmatrix.sync.aligned.m8n8.x4.shared.b16 {%0,%1,%2,%3}, [%4];"\
        : "=r"((R)[0]), "=r"((R)[1]), "=r"((R)[2]), "=r"((R)[3]) : "r"(addr))
#define MMA16816(c, a0, a1, a2, a3, b0, b1)                                     \
    asm volatile("mma.sync.aligned.m16n8k16.row.col.f32.f16.f16.f32 "           \
        "{%0,%1,%2,%3}, {%4,%5,%6,%7}, {%8,%9}, {%0,%1,%2,%3};"                 \
        : "+f"((c)[0]), "+f"((c)[1]), "+f"((c)[2]), "+f"((c)[3])                \
        : "r"(a0), "r"(a1), "r"(a2), "r"(a3), "r"(b0), "r"(b1))

__device__ __forceinline__ float sigf(float x) { return 1.0f / (1.0f + __expf(-x)); }
__device__ __forceinline__ float tanhfast(float x) {
    return 2.0f / (1.0f + __expf(-2.0f * x)) - 1.0f;
}

__device__ __forceinline__ void split8h(const float* v, uint4& hi, uint4& lo) {
    uint32_t hw[4], lw[4];
#pragma unroll
    for (int j = 0; j < 4; j++) {
        __half h0 = __float2half_rn(v[2 * j]), h1 = __float2half_rn(v[2 * j + 1]);
        __half l0 = __float2half_rn(v[2 * j] - __half2float(h0));
        __half l1 = __float2half_rn(v[2 * j + 1] - __half2float(h1));
        hw[j] = (uint32_t)__half_as_ushort(h0) | ((uint32_t)__half_as_ushort(h1) << 16);
        lw[j] = (uint32_t)__half_as_ushort(l0) | ((uint32_t)__half_as_ushort(l1) << 16);
    }
    hi = make_uint4(hw[0], hw[1], hw[2], hw[3]);
    lo = make_uint4(lw[0], lw[1], lw[2], lw[3]);
}

// ---------- prep: U[i][k][n] -> B[n][k] fp16 plane ----------
__global__ __launch_bounds__(256) void gru_prep(const float* __restrict__ Uz,
                                                const float* __restrict__ Ur,
                                                const float* __restrict__ Uh) {
    extern __shared__ float sf[];  // [128][129]
    const int i = blockIdx.x, g = blockIdx.y, tid = threadIdx.x;
    const float* Ui = ((g == 0) ? Uz : (g == 1) ? Ur : Uh) + (size_t)i * D_SZ * D_SZ;
    for (int t = tid; t < D_SZ * D_SZ; t += 256) sf[(t >> 7) * 129 + (t & 127)] = Ui[t];
    __syncthreads();
    unsigned char* hp = g_Uscr + (size_t)(g * 256 + i) * 32768;
    for (int c = tid; c < 2048; c += 256) {
        int n = c >> 4, k0 = (c & 15) * 8;
        uint32_t hw[4];
#pragma unroll
        for (int j = 0; j < 4; j++) {
            __half h0 = __float2half_rn(sf[(k0 + 2 * j) * 129 + n]);      // B[n][k]=U[k][n]
            __half h1 = __float2half_rn(sf[(k0 + 2 * j + 1) * 129 + n]);
            hw[j] = (uint32_t)__half_as_ushort(h0) | ((uint32_t)__half_as_ushort(h1) << 16);
        }
        *(uint4*)(hp + n * 256 + k0 * 2) = make_uint4(hw[0], hw[1], hw[2], hw[3]);
    }
}

// cp.async one U gate (32KB) into a smem buffer
__device__ __forceinline__ void cp_u(uint32_t dst, const unsigned char* src, int tid) {
#pragma unroll
    for (int t = tid; t < 2048; t += 256) {
        uint32_t row = t >> 4, c = t & 15;
        CP16(dst + row * ROWB + c * 16, src + (size_t)t * 16);
    }
    CP_COMMIT();
}

// 2-split GEMM: acc += AH*U + AL*U   (warp tile M=32, N=32, K=128)
__device__ __forceinline__ void gemm2(uint32_t sb, uint32_t ub, int warp_m, int warp_n,
                                      uint32_t offA, uint32_t offB, float acc[2][4][4]) {
#pragma unroll
    for (int mi = 0; mi < 2; mi++)
#pragma unroll
        for (int ni = 0; ni < 4; ni++)
#pragma unroll
            for (int q = 0; q < 4; q++) acc[mi][ni][q] = 0.0f;
#pragma unroll
    for (int ks = 0; ks < 8; ks++) {
        const uint32_t kb = ks * 32;
        uint32_t AH[2][4], AL[2][4], B[2][4];
#pragma unroll
        for (int mi = 0; mi < 2; mi++) {
            uint32_t a = sb + SM_AH + (warp_m + mi * 16) * ROWB + kb + offA;
            LDSM4(AH[mi], a);
            LDSM4(AL[mi], a + A_PLANE);
        }
#pragma unroll
        for (int nj = 0; nj < 2; nj++) {
            uint32_t b = ub + (warp_n + nj * 16) * ROWB + kb + offB;
            LDSM4(B[nj], b);
        }
#pragma unroll
        for (int mi = 0; mi < 2; mi++)
#pragma unroll
            for (int nj = 0; nj < 2; nj++)
#pragma unroll
                for (int hh = 0; hh < 2; hh++) {
                    float* c = acc[mi][nj * 2 + hh];
                    uint32_t b0 = B[nj][hh * 2], b1 = B[nj][hh * 2 + 1];
                    MMA16816(c, AH[mi][0], AH[mi][1], AH[mi][2], AH[mi][3], b0, b1);
                    MMA16816(c, AL[mi][0], AL[mi][1], AL[mi][2], AL[mi][3], b0, b1);
                }
    }
}

// ---------- main fused kernel: M=64 rows/CTA, 2 CTAs/SM, double-buffered U ----------
__global__ __launch_bounds__(256, 2) void gru_main(
    const float* __restrict__ X, const float* __restrict__ hs,
    const float* __restrict__ Wr, const float* __restrict__ Wz, const float* __restrict__ Wh,
    const float* __restrict__ br, const float* __restrict__ bz, const float* __restrict__ bh,
    float* __restrict__ out_hnew, float* __restrict__ out_ht) {
    extern __shared__ __align__(16) unsigned char smem[];
    const uint32_t sb = smem_u32(smem);
    const int tid = threadIdx.x, warp = tid >> 5, l = tid & 31;
    const int i = blockIdx.y, b0 = blockIdx.x * MB;

    float* wb  = (float*)(smem + SM_WB);  // wz|bz|wr|br|wh|bh
    float* x_s = (float*)(smem + SM_X);

    const unsigned char* uz = g_Uscr + (size_t)(0 * 256 + i) * 32768;
    const unsigned char* ur = g_Uscr + (size_t)(1 * 256 + i) * 32768;
    const unsigned char* uh = g_Uscr + (size_t)(2 * 256 + i) * 32768;
    cp_u(sb + SM_U0, uz, tid);   // group 1
    cp_u(sb + SM_U1, ur, tid);   // group 2

    if (tid < 128) {
        wb[tid]       = Wz[i * D_SZ + tid];
        wb[128 + tid] = bz[i * D_SZ + tid];
        wb[256 + tid] = Wr[i * D_SZ + tid];
        wb[384 + tid] = br[i * D_SZ + tid];
        wb[512 + tid] = Wh[i * D_SZ + tid];
        wb[640 + tid] = bh[i * D_SZ + tid];
    }
    if (tid < MB) x_s[tid] = X[(size_t)(b0 + tid) * I_SZ + i];

    // A <= split(hg)  (64 rows x 16 col-chunks)
    for (int c = tid; c < 1024; c += 256) {
        int row = c >> 4, k0 = (c & 15) * 8;
        const float4* g = (const float4*)(hs + (size_t)(b0 + row) * HD + (size_t)i * D_SZ + k0);
        float4 v0 = g[0], v1 = g[1];
        float v[8] = {v0.x, v0.y, v0.z, v0.w, v1.x, v1.y, v1.z, v1.w};
        uint4 hi, lo;
        split8h(v, hi, lo);
        *(uint4*)(smem + SM_AH + row * ROWB + k0 * 2) = hi;
        *(uint4*)(smem + SM_AL + row * ROWB + k0 * 2) = lo;
    }
    CP_WAIT(1);                  // Uz resident (Ur may still be in flight)
    __syncthreads();

    const int warp_m = (warp & 1) * 32, warp_n = (warp >> 1) * 32;
    const uint32_t offA = (uint32_t)((l & 15) * ROWB + (l >> 4) * 16);
    const uint32_t offB = (uint32_t)((l & 7) * ROWB + ((l >> 4) & 1) * (8 * ROWB) +
                                     ((l >> 3) & 1) * 16);
    float acc[2][4][4], z[2][4][4];

    // ---- z gate ----
    gemm2(sb, sb + SM_U0, warp_m, warp_n, offA, offB, acc);
    __syncthreads();             // all warps done reading U0
    cp_u(sb + SM_U0, uh, tid);   // group 3: Uh -> U0, overlaps z epilogue + r gemm
    // z epilogue (registers only)
#pragma unroll
    for (int mi = 0; mi < 2; mi++)
#pragma unroll
        for (int ni = 0; ni < 4; ni++) {
            int col = warp_n + ni * 8 + (l & 3) * 2;
            float w0 = wb[col], w1 = wb[col + 1], c0 = wb[128 + col], c1 = wb[129 + col];
#pragma unroll
            for (int rr = 0; rr < 2; rr++) {
                int row = warp_m + mi * 16 + rr * 8 + (l >> 2);
                float xv = x_s[row];
                z[mi][ni][rr * 2]     = sigf(acc[mi][ni][rr * 2] + xv * w0 + c0);
                z[mi][ni][rr * 2 + 1] = sigf(acc[mi][ni][rr * 2 + 1] + xv * w1 + c1);
            }
        }
    CP_WAIT(1);                  // Ur resident (Uh may still be in flight)
    __syncthreads();

    // ---- r gate ----
    gemm2(sb, sb + SM_U1, warp_m, warp_n, offA, offB, acc);
    __syncthreads();             // all warps done reading A planes

    // r epilogue: hg = AH+AL (exact), A <= split(r*hg) in place
#pragma unroll
    for (int mi = 0; mi < 2; mi++)
#pragma unroll
        for (int ni = 0; ni < 4; ni++) {
            int col = warp_n + ni * 8 + (l & 3) * 2;
            float w0 = wb[256 + col], w1 = wb[257 + col];
            float c0 = wb[384 + col], c1 = wb[385 + col];
#pragma unroll
            for (int rr = 0; rr < 2; rr++) {
                int row = warp_m + mi * 16 + rr * 8 + (l >> 2);
                float xv = x_s[row];
                half2* pH = (half2*)(smem + SM_AH + row * ROWB + col * 2);
                half2* pL = (half2*)(smem + SM_AL + row * ROWB + col * 2);
                half2 hh = *pH, ll = *pL;
                float hg0 = __half2float(__low2half(hh)) + __half2float(__low2half(ll));
                float hg1 = __half2float(__high2half(hh)) + __half2float(__high2half(ll));
                float r0 = sigf(acc[mi][ni][rr * 2] + xv * w0 + c0);
                float r1 = sigf(acc[mi][ni][rr * 2 + 1] + xv * w1 + c1);
                float rh0 = r0 * hg0, rh1 = r1 * hg1;
                __half h0 = __float2half_rn(rh0), h1 = __float2half_rn(rh1);
                *pH = __halves2half2(h0, h1);
                *pL = __halves2half2(__float2half_rn(rh0 - __half2float(h0)),
                                     __float2half_rn(rh1 - __half2float(h1)));
            }
        }
    CP_WAIT(0);                  // Uh resident
    __syncthreads();             // rh planes visible

    // ---- h gate + fused combine ----
    gemm2(sb, sb + SM_U0, warp_m, warp_n, offA, offB, acc);
#pragma unroll
    for (int mi = 0; mi < 2; mi++)
#pragma unroll
        for (int ni = 0; ni < 4; ni++) {
            int col = warp_n + ni * 8 + (l & 3) * 2;
            float w0 = wb[512 + col], w1 = wb[513 + col];
            float c0 = wb[640 + col], c1 = wb[641 + col];
#pragma unroll
            for (int rr = 0; rr < 2; rr++) {
                int row = warp_m + mi * 16 + rr * 8 + (l >> 2);
                float xv = x_s[row];
                size_t gidx = (size_t)(b0 + row) * HD + (size_t)i * D_SZ + col;
                float2 hg = *(const float2*)(hs + gidx);
                float t0 = tanhfast(acc[mi][ni][rr * 2] + xv * w0 + c0);
                float t1 = tanhfast(acc[mi][ni][rr * 2 + 1] + xv * w1 + c1);
                float z0 = z[mi][ni][rr * 2], z1 = z[mi][ni][rr * 2 + 1];
                *(float2*)(out_ht + gidx)   = make_float2(t0, t1);
                *(float2*)(out_hnew + gidx) = make_float2(z0 * hg.x + (1.0f - z0) * t0,
                                                          z1 * hg.y + (1.0f - z1) * t1);
            }
        }
}

extern "C" void kernel_launch(void* const* d_in, const int* in_sizes, int n_in,
                              void* d_out, int out_size) {
    const float* X  = (const float*)d_in[0];
    const float* h  = (const float*)d_in[1];
    const float* Wr = (const float*)d_in[2];
    const float* Wz = (const float*)d_in[3];
    const float* Wh = (const float*)d_in[4];
    const float* Ur = (const float*)d_in[5];
    const float* Uz = (const float*)d_in[6];
    const float* Uh = (const float*)d_in[7];
    const float* br = (const float*)d_in[8];
    const float* bz = (const float*)d_in[9];
    const float* bh = (const float*)d_in[10];
    float* out = (float*)d_out;
    float* out_hnew = out;
    float* out_ht   = out + (size_t)1024 * HD;

    cudaFuncSetAttribute(gru_prep, cudaFuncAttributeMaxDynamicSharedMemorySize, 128 * 129 * 4);
    cudaFuncSetAttribute(gru_main, cudaFuncAttributeMaxDynamicSharedMemorySize, (int)SMEM_MAIN);

    gru_prep<<<dim3(256, 3), 256, 128 * 129 * 4>>>(Uz, Ur, Uh);
    gru_main<<<dim3(16, 256), 256, SMEM_MAIN>>>(X, h, Wr, Wz, Wh, br, bz, bh,
                                                out_hnew, out_ht);
}